// round 3
// baseline (speedup 1.0000x reference)
#include <cuda_runtime.h>
#include <cuda_bf16.h>
#include <math.h>

// Problem dims (fixed by the dataset)
#define SS 128      // sequence length
#define BB 64       // batch
#define HH 1024     // hidden = embedding dim
#define VV 10000    // vocab
#define MM (SS*BB)  // 8192 rows for the batched GEMMs
#define BH (BB*HH)  // 65536
#define GRIDN 128   // persistent kernel grid (16 j-tiles x 8 k-chunks)

// ---------------- device scratch (no allocations allowed) ----------------
__device__ float g_pre0[MM * HH];   // precomputed emb@W_ih0^T + b_ih0 for all steps
__device__ float g_X[MM * HH];      // layer-1 outputs for all steps (input to logits GEMM)
__device__ float g_acc0[2][BH];     // ping-pong partial-sum accumulators, layer 0
__device__ float g_acc1[2][BH];     // ping-pong partial-sum accumulators, layer 1
__device__ unsigned g_arrive;       // grid barrier: monotonic arrival counter
__device__ unsigned g_release;      // grid barrier: released generation

// ---------------- L2-coherent loads (L1 is not coherent across SMs) -------
__device__ __forceinline__ float ldcg_f(const float* p) {
    float v; asm volatile("ld.global.cg.f32 %0, [%1];" : "=f"(v) : "l"(p)); return v;
}
__device__ __forceinline__ unsigned ldcg_u(const unsigned* p) {
    unsigned v; asm volatile("ld.global.cg.u32 %0, [%1];" : "=r"(v) : "l"(p)); return v;
}

// ---------------- grid-wide barrier (all GRIDN blocks resident) ----------
__device__ __forceinline__ void grid_barrier(unsigned want) {
    __syncthreads();                       // all block work done (incl. atomics issued+visible)
    if (threadIdx.x == 0) {
        __threadfence();
        unsigned prev = atomicAdd(&g_arrive, 1u);
        if (prev == want * GRIDN - 1u) {
            atomicExch(&g_release, want);  // last arriver publishes generation
        }
        while (ldcg_u(&g_release) < want) { __nanosleep(64); }
    }
    __syncthreads();
}

// ---------------- generic tiled fp32 GEMM: C = A @ B^T + bias ----------------
// A: [M,K] row-major (or gathered rows of emb when GATHER), B: [N,K] row-major.
// BM=BN=128, BK=16, 256 threads, 8x8 per thread. M mult of 128, K mult of 16,
// N bounds-checked (V=10000).
template<bool GATHER>
__global__ void __launch_bounds__(256) sgemm_tn(
    const float* __restrict__ A,
    const float* __restrict__ emb,
    const int*   __restrict__ gidx,
    float scaleA,
    const float* __restrict__ Bm,
    const float* __restrict__ bias,
    float* __restrict__ C, int ldc,
    int N, int K)
{
    __shared__ float As[16][128 + 4];
    __shared__ float Bs[16][128 + 4];

    const int bm = blockIdx.y * 128;
    const int bn = blockIdx.x * 128;
    const int tid = threadIdx.x;
    const int tx = tid & 15;        // n-group
    const int ty = tid >> 4;        // m-group
    const int lr0 = tid >> 2;       // 0..63
    const int lr1 = lr0 + 64;       // 64..127
    const int lc4 = (tid & 3) * 4;  // 0,4,8,12

    const float* arow0;
    const float* arow1;
    if (GATHER) {
        arow0 = emb + (size_t)gidx[bm + lr0] * K;
        arow1 = emb + (size_t)gidx[bm + lr1] * K;
    } else {
        arow0 = A + (size_t)(bm + lr0) * K;
        arow1 = A + (size_t)(bm + lr1) * K;
    }
    const int  bn0 = bn + lr0, bn1 = bn + lr1;
    const bool v0 = bn0 < N, v1 = bn1 < N;
    const float* brow0 = Bm + (size_t)bn0 * K;
    const float* brow1 = Bm + (size_t)bn1 * K;

    float acc[8][8] = {};

    for (int k0 = 0; k0 < K; k0 += 16) {
        float4 a0 = *(const float4*)(arow0 + k0 + lc4);
        float4 a1 = *(const float4*)(arow1 + k0 + lc4);
        if (GATHER) {
            a0.x *= scaleA; a0.y *= scaleA; a0.z *= scaleA; a0.w *= scaleA;
            a1.x *= scaleA; a1.y *= scaleA; a1.z *= scaleA; a1.w *= scaleA;
        }
        float4 b0 = v0 ? *(const float4*)(brow0 + k0 + lc4) : make_float4(0.f,0.f,0.f,0.f);
        float4 b1 = v1 ? *(const float4*)(brow1 + k0 + lc4) : make_float4(0.f,0.f,0.f,0.f);

        As[lc4+0][lr0] = a0.x; As[lc4+1][lr0] = a0.y; As[lc4+2][lr0] = a0.z; As[lc4+3][lr0] = a0.w;
        As[lc4+0][lr1] = a1.x; As[lc4+1][lr1] = a1.y; As[lc4+2][lr1] = a1.z; As[lc4+3][lr1] = a1.w;
        Bs[lc4+0][lr0] = b0.x; Bs[lc4+1][lr0] = b0.y; Bs[lc4+2][lr0] = b0.z; Bs[lc4+3][lr0] = b0.w;
        Bs[lc4+0][lr1] = b1.x; Bs[lc4+1][lr1] = b1.y; Bs[lc4+2][lr1] = b1.z; Bs[lc4+3][lr1] = b1.w;
        __syncthreads();

        #pragma unroll
        for (int kk = 0; kk < 16; kk++) {
            float4 av0 = *(const float4*)&As[kk][ty*8];
            float4 av1 = *(const float4*)&As[kk][ty*8 + 4];
            float4 bw0 = *(const float4*)&Bs[kk][tx*8];
            float4 bw1 = *(const float4*)&Bs[kk][tx*8 + 4];
            float a[8] = {av0.x, av0.y, av0.z, av0.w, av1.x, av1.y, av1.z, av1.w};
            float b[8] = {bw0.x, bw0.y, bw0.z, bw0.w, bw1.x, bw1.y, bw1.z, bw1.w};
            #pragma unroll
            for (int i = 0; i < 8; i++)
                #pragma unroll
                for (int j = 0; j < 8; j++)
                    acc[i][j] = fmaf(a[i], b[j], acc[i][j]);
        }
        __syncthreads();
    }

    #pragma unroll
    for (int i = 0; i < 8; i++) {
        const int m = bm + ty*8 + i;
        #pragma unroll
        for (int j = 0; j < 8; j++) {
            const int n = bn + tx*8 + j;
            if (n < N) C[(size_t)m * ldc + n] = acc[i][j] + bias[n];
        }
    }
}

// ---------------- persistent recurrence kernel ----------------
// 128 blocks (16 j-tiles x 8 k-chunks), 512 threads, weights + h-state in SMEM.
// Per step:
//   phase1: acc0[p] += h0 @ W_hh0^T (partial), acc1[p] += h1 @ W_hh1^T (partial)
//   [grid barrier]
//   phase2: h0' = tanh(acc0[p] + pre0[t] + b_hh0)  (each block computes its k-slice)
//           zero acc*[1-p]; acc1[p] += h0' @ W_ih1^T (partial)
//   [grid barrier]
//   phase3: h1' = tanh(acc1[p] + b_ih1 + b_hh1); jt==0 blocks write X[t]
// SMEM per block: 3x W tile [128k][68 pad] + 2x h slice [128k][65 pad] + biases ~168 KB.
#define W_LD 68   // padded j-stride for W tiles (16B aligned rows, conflict-free reads)
#define H_LD 65   // padded b-stride for h slices (conflict-free k-major stores)
#define SMEM_FLOATS (3*128*W_LD + 2*128*H_LD + 256)

__global__ void __launch_bounds__(512, 1) rnn_persist(
    const float* __restrict__ hidden,
    const float* __restrict__ pre0,
    const float* __restrict__ Whh0,
    const float* __restrict__ Wih1,
    const float* __restrict__ Whh1,
    const float* __restrict__ bhh0,
    const float* __restrict__ bih1,
    const float* __restrict__ bhh1,
    float* __restrict__ X,
    float* __restrict__ outh)
{
    extern __shared__ float sm[];
    float* Wh0 = sm;                      // [128][W_LD]  (k-major, j fast)
    float* Wi1 = Wh0 + 128 * W_LD;
    float* Wh1 = Wi1 + 128 * W_LD;
    float* H0  = Wh1 + 128 * W_LD;        // [128][H_LD]  (k-major, b fast)
    float* H1  = H0  + 128 * H_LD;
    float* B0  = H1  + 128 * H_LD;        // b_hh0 slice (128)
    float* B1  = B0  + 128;               // b_ih1+b_hh1 slice (128)

    const int tid = threadIdx.x;
    const int jt  = blockIdx.x >> 3;      // 0..15 : output j-tile (64 wide)
    const int kc  = blockIdx.x & 7;       // 0..7  : input k-chunk (128 wide); also tanh j-range
    const int j0g = jt * 64;
    const int k0g = kc * 128;

    // ---- one-time loads: weight tiles (k-major in SMEM), biases, initial h
    for (int idx = tid; idx < 64 * 128; idx += 512) {
        const int j = idx >> 7, k = idx & 127;
        const size_t g = (size_t)(j0g + j) * HH + k0g + k;
        Wh0[k * W_LD + j] = Whh0[g];
        Wi1[k * W_LD + j] = Wih1[g];
        Wh1[k * W_LD + j] = Whh1[g];
    }
    if (tid < 128) {
        B0[tid] = bhh0[k0g + tid];
        B1[tid] = bih1[k0g + tid] + bhh1[k0g + tid];
    }
    for (int idx = tid; idx < 64 * 128; idx += 512) {
        const int k = idx >> 6, b = idx & 63;
        H0[k * H_LD + b] = hidden[(size_t)b * HH + k0g + k];
        H1[k * H_LD + b] = hidden[(size_t)BH + (size_t)b * HH + k0g + k];
    }
    __syncthreads();

    const int tx = tid & 15;   // 4 j's each
    const int ty = tid >> 4;   // 2 b's each
    const int jq = tx * 4;
    const int b2 = ty * 2;

    unsigned barnum = 0;

    for (int t = 0; t < SS; t++) {
        const int p = t & 1;
        float* acc0 = &g_acc0[p][0];
        float* acc1 = &g_acc1[p][0];

        // ---------------- phase 1: h0@Whh0 and h1@Whh1 partials -------------
        {
            float r0[2][4] = {}, r1[2][4] = {};
            #pragma unroll 2
            for (int k = 0; k < 128; ++k) {
                const float h0a = H0[k * H_LD + b2];
                const float h0b = H0[k * H_LD + b2 + 1];
                const float h1a = H1[k * H_LD + b2];
                const float h1b = H1[k * H_LD + b2 + 1];
                const float4 w0 = *(const float4*)&Wh0[k * W_LD + jq];
                const float4 w1 = *(const float4*)&Wh1[k * W_LD + jq];
                const float w0a[4] = {w0.x, w0.y, w0.z, w0.w};
                const float w1a[4] = {w1.x, w1.y, w1.z, w1.w};
                #pragma unroll
                for (int j = 0; j < 4; j++) {
                    r0[0][j] = fmaf(h0a, w0a[j], r0[0][j]);
                    r0[1][j] = fmaf(h0b, w0a[j], r0[1][j]);
                    r1[0][j] = fmaf(h1a, w1a[j], r1[0][j]);
                    r1[1][j] = fmaf(h1b, w1a[j], r1[1][j]);
                }
            }
            #pragma unroll
            for (int i = 0; i < 2; i++)
                #pragma unroll
                for (int j = 0; j < 4; j++) {
                    const size_t o = (size_t)(b2 + i) * HH + j0g + jq + j;
                    atomicAdd(&acc0[o], r0[i][j]);
                    atomicAdd(&acc1[o], r1[i][j]);
                }
        }
        grid_barrier(++barnum);

        // ---------------- phase 2: tanh layer0, zero next accs, h0'@Wih1 ----
        {
            const float* pt = pre0 + (size_t)t * BH;
            for (int idx = tid; idx < 64 * 128; idx += 512) {
                const int b = idx >> 7, kk = idx & 127;
                const size_t o = (size_t)b * HH + k0g + kk;
                const float v = ldcg_f(&acc0[o]) + pt[o] + B0[kk];
                H0[kk * H_LD + b] = tanhf(v);
            }
            // zero next-parity accumulators (1 elem per thread per array)
            const int zi = (int)blockIdx.x * 512 + tid;   // covers exactly BH
            g_acc0[1 - p][zi] = 0.0f;
            g_acc1[1 - p][zi] = 0.0f;
            __syncthreads();

            float r[2][4] = {};
            #pragma unroll 2
            for (int k = 0; k < 128; ++k) {
                const float xa = H0[k * H_LD + b2];
                const float xb = H0[k * H_LD + b2 + 1];
                const float4 w = *(const float4*)&Wi1[k * W_LD + jq];
                const float wa[4] = {w.x, w.y, w.z, w.w};
                #pragma unroll
                for (int j = 0; j < 4; j++) {
                    r[0][j] = fmaf(xa, wa[j], r[0][j]);
                    r[1][j] = fmaf(xb, wa[j], r[1][j]);
                }
            }
            #pragma unroll
            for (int i = 0; i < 2; i++)
                #pragma unroll
                for (int j = 0; j < 4; j++)
                    atomicAdd(&acc1[(size_t)(b2 + i) * HH + j0g + jq + j], r[i][j]);
        }
        grid_barrier(++barnum);

        // ---------------- phase 3: tanh layer1, write X[t] -------------------
        {
            float* Xt = X + (size_t)t * BH;
            for (int idx = tid; idx < 64 * 128; idx += 512) {
                const int b = idx >> 7, kk = idx & 127;
                const size_t o = (size_t)b * HH + k0g + kk;
                const float v = ldcg_f(&acc1[o]) + B1[kk];
                const float th = tanhf(v);
                H1[kk * H_LD + b] = th;
                if (jt == 0) Xt[o] = th;
            }
            __syncthreads();   // H1 ready for next step's phase 1
        }
    }

    // ---- final hidden state: h_final = [h0, h1]
    if (outh != nullptr && jt == 0) {
        for (int idx = tid; idx < 64 * 128; idx += 512) {
            const int b = idx >> 7, kk = idx & 127;
            const size_t o = (size_t)b * HH + k0g + kk;
            outh[o]      = H0[kk * H_LD + b];
            outh[BH + o] = H1[kk * H_LD + b];
        }
    }
}

// ---------------- init: zero accumulators + barrier state ----------------
__global__ void __launch_bounds__(256) init_kernel()
{
    const int i = blockIdx.x * 256 + threadIdx.x;   // grid covers 2*BH
    g_acc0[0][i & (BH - 1)] = 0.0f;   // covered twice; harmless & uniform
    g_acc0[1][i & (BH - 1)] = 0.0f;
    g_acc1[0][i & (BH - 1)] = 0.0f;
    g_acc1[1][i & (BH - 1)] = 0.0f;
    if (i == 0) { g_arrive = 0u; g_release = 0u; }
}

// ---------------- launcher ----------------
extern "C" void kernel_launch(void* const* d_in, const int* in_sizes, int n_in,
                              void* d_out, int out_size)
{
    const int*   inputs = (const int*)  d_in[0];  // [S,B]
    const float* hidden = (const float*)d_in[1];  // [L,B,H]
    const float* emb    = (const float*)d_in[2];  // [V,E]
    const float* W_ih   = (const float*)d_in[3];  // [L,H,E]
    const float* b_ih   = (const float*)d_in[4];  // [L,H]
    const float* W_hh   = (const float*)d_in[5];  // [L,H,H]
    const float* b_hh   = (const float*)d_in[6];  // [L,H]
    const float* W_out  = (const float*)d_in[7];  // [V,H]
    const float* b_out  = (const float*)d_in[8];  // [V]

    const float* W_ih0 = W_ih;
    const float* W_ih1 = W_ih + (size_t)HH * HH;
    const float* W_hh0 = W_hh;
    const float* W_hh1 = W_hh + (size_t)HH * HH;
    const float* b_ih0 = b_ih;
    const float* b_ih1 = b_ih + HH;
    const float* b_hh0 = b_hh;
    const float* b_hh1 = b_hh + HH;

    float *pre0, *X;
    cudaGetSymbolAddress((void**)&pre0, g_pre0);
    cudaGetSymbolAddress((void**)&X,    g_X);

    float* out = (float*)d_out;
    const long long logitsN = (long long)MM * VV;
    float* outh = ((long long)out_size >= logitsN + 2LL * BH) ? out + logitsN : nullptr;

    // persistent kernel needs >48KB dynamic smem
    const int smem_bytes = SMEM_FLOATS * (int)sizeof(float);
    cudaFuncSetAttribute(rnn_persist, cudaFuncAttributeMaxDynamicSharedMemorySize, smem_bytes);

    // init accumulators + barrier counters (runs every replay)
    init_kernel<<<BH/256, 256>>>();

    // Phase A: pre0 = (emb[tok]*sqrt(E)) @ W_ih0^T + b_ih0   (M=8192,N=1024,K=1024)
    {
        dim3 g(HH/128, MM/128);
        sgemm_tn<true><<<g, 256>>>(nullptr, emb, inputs, 32.0f,
                                   W_ih0, b_ih0, pre0, HH, HH, HH);
    }

    // Phase B: persistent recurrence (one launch for all 128 steps)
    rnn_persist<<<GRIDN, 512, smem_bytes>>>(hidden, pre0,
                                            W_hh0, W_ih1, W_hh1,
                                            b_hh0, b_ih1, b_hh1,
                                            X, outh);

    // Phase C: logits = X @ W_out^T + b_out   (M=8192, N=10000, K=1024)
    {
        dim3 g((VV + 127) / 128, MM / 128);
        sgemm_tn<false><<<g, 256>>>(X, nullptr, nullptr, 1.0f,
                                    W_out, b_out, out, VV, VV, HH);
    }
}

// round 4
// speedup vs baseline: 1.1469x; 1.1469x over previous
#include <cuda_runtime.h>
#include <cuda_bf16.h>
#include <math.h>

// Problem dims (fixed by the dataset)
#define SS 128      // sequence length
#define BB 64       // batch
#define HH 1024     // hidden = embedding dim
#define VV 10000    // vocab
#define MM (SS*BB)  // 8192 rows for the batched GEMMs
#define BH (BB*HH)  // 65536
#define GRIDN 128   // persistent kernel grid (16 j-tiles x 8 k-chunks)

// ---------------- device scratch (no allocations allowed) ----------------
__device__ __align__(16) float g_pre0[MM * HH];     // emb@W_ih0^T + b_ih0, all steps
__device__ __align__(16) float g_X[MM * HH];        // layer-1 outputs, all steps
__device__ __align__(16) float g_p0[2][8][BH];      // partials: h0@Whh0 (parity, k-chunk)
__device__ __align__(16) float g_p1[2][8][BH];      // partials: h1@Whh1
__device__ __align__(16) float g_p2[2][8][BH];      // partials: h0'@Wih1
__device__ unsigned g_arrive;                       // grid barrier: arrival counter
__device__ unsigned g_release;                      // grid barrier: released generation

// ---------------- L2-scope loads (L1 is stale across SMs / steps) ---------
__device__ __forceinline__ float4 ldcg4(const float* p) {
    float4 v;
    asm volatile("ld.global.cg.v4.f32 {%0,%1,%2,%3}, [%4];"
                 : "=f"(v.x), "=f"(v.y), "=f"(v.z), "=f"(v.w) : "l"(p));
    return v;
}
__device__ __forceinline__ unsigned ldcg_u(const unsigned* p) {
    unsigned v; asm volatile("ld.global.cg.u32 %0, [%1];" : "=r"(v) : "l"(p)); return v;
}

// ---------------- grid-wide barrier (all GRIDN blocks resident) ----------
__device__ __forceinline__ void grid_barrier(unsigned want) {
    __syncthreads();
    if (threadIdx.x == 0) {
        __threadfence();
        unsigned prev = atomicAdd(&g_arrive, 1u);
        if (prev == want * GRIDN - 1u) {
            atomicExch(&g_release, want);
        }
        while (ldcg_u(&g_release) < want) { __nanosleep(32); }
    }
    __syncthreads();
}

// ---------------- generic tiled fp32 GEMM: C = A @ B^T + bias ----------------
template<bool GATHER>
__global__ void __launch_bounds__(256) sgemm_tn(
    const float* __restrict__ A,
    const float* __restrict__ emb,
    const int*   __restrict__ gidx,
    float scaleA,
    const float* __restrict__ Bm,
    const float* __restrict__ bias,
    float* __restrict__ C, int ldc,
    int N, int K)
{
    __shared__ float As[16][128 + 4];
    __shared__ float Bs[16][128 + 4];

    const int bm = blockIdx.y * 128;
    const int bn = blockIdx.x * 128;
    const int tid = threadIdx.x;
    const int tx = tid & 15;
    const int ty = tid >> 4;
    const int lr0 = tid >> 2;
    const int lr1 = lr0 + 64;
    const int lc4 = (tid & 3) * 4;

    const float* arow0;
    const float* arow1;
    if (GATHER) {
        arow0 = emb + (size_t)gidx[bm + lr0] * K;
        arow1 = emb + (size_t)gidx[bm + lr1] * K;
    } else {
        arow0 = A + (size_t)(bm + lr0) * K;
        arow1 = A + (size_t)(bm + lr1) * K;
    }
    const int  bn0 = bn + lr0, bn1 = bn + lr1;
    const bool v0 = bn0 < N, v1 = bn1 < N;
    const float* brow0 = Bm + (size_t)bn0 * K;
    const float* brow1 = Bm + (size_t)bn1 * K;

    float acc[8][8] = {};

    for (int k0 = 0; k0 < K; k0 += 16) {
        float4 a0 = *(const float4*)(arow0 + k0 + lc4);
        float4 a1 = *(const float4*)(arow1 + k0 + lc4);
        if (GATHER) {
            a0.x *= scaleA; a0.y *= scaleA; a0.z *= scaleA; a0.w *= scaleA;
            a1.x *= scaleA; a1.y *= scaleA; a1.z *= scaleA; a1.w *= scaleA;
        }
        float4 b0 = v0 ? *(const float4*)(brow0 + k0 + lc4) : make_float4(0.f,0.f,0.f,0.f);
        float4 b1 = v1 ? *(const float4*)(brow1 + k0 + lc4) : make_float4(0.f,0.f,0.f,0.f);

        As[lc4+0][lr0] = a0.x; As[lc4+1][lr0] = a0.y; As[lc4+2][lr0] = a0.z; As[lc4+3][lr0] = a0.w;
        As[lc4+0][lr1] = a1.x; As[lc4+1][lr1] = a1.y; As[lc4+2][lr1] = a1.z; As[lc4+3][lr1] = a1.w;
        Bs[lc4+0][lr0] = b0.x; Bs[lc4+1][lr0] = b0.y; Bs[lc4+2][lr0] = b0.z; Bs[lc4+3][lr0] = b0.w;
        Bs[lc4+0][lr1] = b1.x; Bs[lc4+1][lr1] = b1.y; Bs[lc4+2][lr1] = b1.z; Bs[lc4+3][lr1] = b1.w;
        __syncthreads();

        #pragma unroll
        for (int kk = 0; kk < 16; kk++) {
            float4 av0 = *(const float4*)&As[kk][ty*8];
            float4 av1 = *(const float4*)&As[kk][ty*8 + 4];
            float4 bw0 = *(const float4*)&Bs[kk][tx*8];
            float4 bw1 = *(const float4*)&Bs[kk][tx*8 + 4];
            float a[8] = {av0.x, av0.y, av0.z, av0.w, av1.x, av1.y, av1.z, av1.w};
            float b[8] = {bw0.x, bw0.y, bw0.z, bw0.w, bw1.x, bw1.y, bw1.z, bw1.w};
            #pragma unroll
            for (int i = 0; i < 8; i++)
                #pragma unroll
                for (int j = 0; j < 8; j++)
                    acc[i][j] = fmaf(a[i], b[j], acc[i][j]);
        }
        __syncthreads();
    }

    #pragma unroll
    for (int i = 0; i < 8; i++) {
        const int m = bm + ty*8 + i;
        #pragma unroll
        for (int j = 0; j < 8; j++) {
            const int n = bn + tx*8 + j;
            if (n < N) C[(size_t)m * ldc + n] = acc[i][j] + bias[n];
        }
    }
}

// ---------------- persistent recurrence kernel (ATOMIC-FREE) ----------------
// 128 blocks (16 j-tiles x 8 k-chunks of 128), 512 threads.
// Weights k-major in SMEM, h-state b-major in SMEM.
// Per step:
//   phase1: p0[kc] = h0-tile @ Whh0-tile, p1[kc] = h1-tile @ Whh1-tile (vec4 STG)
//   [barrier]
//   phase2: reduce p0(8 planes)+pre0[t]+b -> tanh -> H0 smem;
//           reduce p1 -> stash in H1 smem;  then p2[kc] = H0 @ Wih1-tile
//   [barrier]
//   phase3: H1 = tanh(H1stash + reduce p2 + b); jt==0 writes X[t]
#define W_LD  68    // j-stride for weight tiles [128k][64j] (pad, 16B aligned)
#define HB_LD 132   // k-stride for h tiles [64b][128k] (pad, 16B aligned)
#define SMEM_FLOATS (3*128*W_LD + 2*64*HB_LD + 256)

__global__ void __launch_bounds__(512, 1) rnn_persist(
    const float* __restrict__ hidden,
    const float* __restrict__ pre0,
    const float* __restrict__ Whh0,
    const float* __restrict__ Wih1,
    const float* __restrict__ Whh1,
    const float* __restrict__ bhh0,
    const float* __restrict__ bih1,
    const float* __restrict__ bhh1,
    float* __restrict__ X,
    float* __restrict__ outh)
{
    extern __shared__ float sm[];
    float* Wh0 = sm;                      // [128][W_LD] k-major
    float* Wi1 = Wh0 + 128 * W_LD;
    float* Wh1 = Wi1 + 128 * W_LD;
    float* H0s = Wh1 + 128 * W_LD;        // [64][HB_LD] b-major
    float* H1s = H0s + 64 * HB_LD;
    float* B0s = H1s + 64 * HB_LD;        // b_hh0 slice (128)
    float* B1s = B0s + 128;               // b_ih1+b_hh1 slice (128)

    const int tid = threadIdx.x;
    const int jt  = blockIdx.x >> 3;      // 0..15 : output j-tile (64 wide)
    const int kc  = blockIdx.x & 7;       // 0..7  : k-chunk (128 wide)
    const int j0g = jt * 64;
    const int k0g = kc * 128;

    // ---- one-time loads
    for (int idx = tid; idx < 64 * 128; idx += 512) {
        const int j = idx >> 7, k = idx & 127;
        const size_t g = (size_t)(j0g + j) * HH + k0g + k;
        Wh0[k * W_LD + j] = Whh0[g];
        Wi1[k * W_LD + j] = Wih1[g];
        Wh1[k * W_LD + j] = Whh1[g];
    }
    if (tid < 128) {
        B0s[tid] = bhh0[k0g + tid];
        B1s[tid] = bih1[k0g + tid] + bhh1[k0g + tid];
    }
    {
        const int lane = tid & 31, wrp = tid >> 5;   // 16 warps
        for (int b = wrp; b < 64; b += 16) {
            const int kk = lane * 4;
            float4 h0 = *(const float4*)&hidden[(size_t)b * HH + k0g + kk];
            float4 h1 = *(const float4*)&hidden[(size_t)BH + (size_t)b * HH + k0g + kk];
            *(float4*)&H0s[b * HB_LD + kk] = h0;
            *(float4*)&H1s[b * HB_LD + kk] = h1;
        }
    }
    __syncthreads();

    const int tx = tid & 15;   // 4 j's each
    const int ty = tid >> 4;   // 2 b's each
    const int jq = tx * 4;
    const int b2 = ty * 2;
    const int lane = tid & 31, wrp = tid >> 5;

    unsigned barnum = 0;

    for (int t = 0; t < SS; t++) {
        const int p = t & 1;
        float* p0 = &g_p0[p][kc][0];
        float* p1 = &g_p1[p][kc][0];
        float* p2 = &g_p2[p][kc][0];

        // ---------------- phase 1: both recurrent GEMM partials -------------
        {
            float r0[2][4] = {}, r1[2][4] = {};
            #pragma unroll 4
            for (int k = 0; k < 128; ++k) {
                const float h0a = H0s[b2 * HB_LD + k];
                const float h0b = H0s[(b2 + 1) * HB_LD + k];
                const float h1a = H1s[b2 * HB_LD + k];
                const float h1b = H1s[(b2 + 1) * HB_LD + k];
                const float4 w0 = *(const float4*)&Wh0[k * W_LD + jq];
                const float4 w1 = *(const float4*)&Wh1[k * W_LD + jq];
                const float w0a[4] = {w0.x, w0.y, w0.z, w0.w};
                const float w1a[4] = {w1.x, w1.y, w1.z, w1.w};
                #pragma unroll
                for (int j = 0; j < 4; j++) {
                    r0[0][j] = fmaf(h0a, w0a[j], r0[0][j]);
                    r0[1][j] = fmaf(h0b, w0a[j], r0[1][j]);
                    r1[0][j] = fmaf(h1a, w1a[j], r1[0][j]);
                    r1[1][j] = fmaf(h1b, w1a[j], r1[1][j]);
                }
            }
            #pragma unroll
            for (int i = 0; i < 2; i++) {
                const size_t o = (size_t)(b2 + i) * HH + j0g + jq;
                *(float4*)&p0[o] = make_float4(r0[i][0], r0[i][1], r0[i][2], r0[i][3]);
                *(float4*)&p1[o] = make_float4(r1[i][0], r1[i][1], r1[i][2], r1[i][3]);
            }
        }
        grid_barrier(++barnum);

        // ---------------- phase 2: reduce+tanh layer0, stash l1-sum, GEMM ---
        {
            const float* pt = pre0 + (size_t)t * BH;
            const float* P0 = &g_p0[p][0][0];
            const float* P1 = &g_p1[p][0][0];
            for (int b = wrp; b < 64; b += 16) {
                const int kk = lane * 4;
                const int kg = k0g + kk;
                float4 s0 = *(const float4*)&pt[(size_t)b * HH + kg];
                const float4 bb = *(const float4*)&B0s[kk];
                s0.x += bb.x; s0.y += bb.y; s0.z += bb.z; s0.w += bb.w;
                float4 s1 = make_float4(0.f, 0.f, 0.f, 0.f);
                #pragma unroll
                for (int kcc = 0; kcc < 8; kcc++) {
                    const size_t o = (size_t)kcc * BH + (size_t)b * HH + kg;
                    float4 a = ldcg4(P0 + o);
                    s0.x += a.x; s0.y += a.y; s0.z += a.z; s0.w += a.w;
                    float4 c = ldcg4(P1 + o);
                    s1.x += c.x; s1.y += c.y; s1.z += c.z; s1.w += c.w;
                }
                float4 th = make_float4(tanhf(s0.x), tanhf(s0.y), tanhf(s0.z), tanhf(s0.w));
                *(float4*)&H0s[b * HB_LD + kk] = th;
                *(float4*)&H1s[b * HB_LD + kk] = s1;   // stash pre-activation l1 sum
            }
            __syncthreads();

            float r[2][4] = {};
            #pragma unroll 4
            for (int k = 0; k < 128; ++k) {
                const float xa = H0s[b2 * HB_LD + k];
                const float xb = H0s[(b2 + 1) * HB_LD + k];
                const float4 w = *(const float4*)&Wi1[k * W_LD + jq];
                const float wa[4] = {w.x, w.y, w.z, w.w};
                #pragma unroll
                for (int j = 0; j < 4; j++) {
                    r[0][j] = fmaf(xa, wa[j], r[0][j]);
                    r[1][j] = fmaf(xb, wa[j], r[1][j]);
                }
            }
            #pragma unroll
            for (int i = 0; i < 2; i++) {
                const size_t o = (size_t)(b2 + i) * HH + j0g + jq;
                *(float4*)&p2[o] = make_float4(r[i][0], r[i][1], r[i][2], r[i][3]);
            }
        }
        grid_barrier(++barnum);

        // ---------------- phase 3: reduce + tanh layer1, write X[t] ----------
        {
            float* Xt = X + (size_t)t * BH;
            const float* P2 = &g_p2[p][0][0];
            for (int b = wrp; b < 64; b += 16) {
                const int kk = lane * 4;
                const int kg = k0g + kk;
                float4 s = *(const float4*)&H1s[b * HB_LD + kk];   // stash
                const float4 bb = *(const float4*)&B1s[kk];
                s.x += bb.x; s.y += bb.y; s.z += bb.z; s.w += bb.w;
                #pragma unroll
                for (int kcc = 0; kcc < 8; kcc++) {
                    const size_t o = (size_t)kcc * BH + (size_t)b * HH + kg;
                    float4 a = ldcg4(P2 + o);
                    s.x += a.x; s.y += a.y; s.z += a.z; s.w += a.w;
                }
                float4 th = make_float4(tanhf(s.x), tanhf(s.y), tanhf(s.z), tanhf(s.w));
                *(float4*)&H1s[b * HB_LD + kk] = th;
                if (jt == 0) *(float4*)&Xt[(size_t)b * HH + kg] = th;
            }
            __syncthreads();   // H1s ready for next step's phase 1
        }
    }

    // ---- final hidden state: h_final = [h0, h1]
    if (outh != nullptr && jt == 0) {
        for (int b = wrp; b < 64; b += 16) {
            const int kk = lane * 4;
            const int kg = k0g + kk;
            *(float4*)&outh[(size_t)b * HH + kg]      = *(const float4*)&H0s[b * HB_LD + kk];
            *(float4*)&outh[BH + (size_t)b * HH + kg] = *(const float4*)&H1s[b * HB_LD + kk];
        }
    }
}

// ---------------- init: reset barrier state each replay ----------------
__global__ void init_kernel()
{
    g_arrive = 0u;
    g_release = 0u;
}

// ---------------- launcher ----------------
extern "C" void kernel_launch(void* const* d_in, const int* in_sizes, int n_in,
                              void* d_out, int out_size)
{
    const int*   inputs = (const int*)  d_in[0];  // [S,B]
    const float* hidden = (const float*)d_in[1];  // [L,B,H]
    const float* emb    = (const float*)d_in[2];  // [V,E]
    const float* W_ih   = (const float*)d_in[3];  // [L,H,E]
    const float* b_ih   = (const float*)d_in[4];  // [L,H]
    const float* W_hh   = (const float*)d_in[5];  // [L,H,H]
    const float* b_hh   = (const float*)d_in[6];  // [L,H]
    const float* W_out  = (const float*)d_in[7];  // [V,H]
    const float* b_out  = (const float*)d_in[8];  // [V]

    const float* W_ih0 = W_ih;
    const float* W_ih1 = W_ih + (size_t)HH * HH;
    const float* W_hh0 = W_hh;
    const float* W_hh1 = W_hh + (size_t)HH * HH;
    const float* b_ih0 = b_ih;
    const float* b_ih1 = b_ih + HH;
    const float* b_hh0 = b_hh;
    const float* b_hh1 = b_hh + HH;

    float *pre0, *X;
    cudaGetSymbolAddress((void**)&pre0, g_pre0);
    cudaGetSymbolAddress((void**)&X,    g_X);

    float* out = (float*)d_out;
    const long long logitsN = (long long)MM * VV;
    float* outh = ((long long)out_size >= logitsN + 2LL * BH) ? out + logitsN : nullptr;

    const int smem_bytes = SMEM_FLOATS * (int)sizeof(float);
    cudaFuncSetAttribute(rnn_persist, cudaFuncAttributeMaxDynamicSharedMemorySize, smem_bytes);

    // reset barrier counters (runs every replay)
    init_kernel<<<1, 1>>>();

    // Phase A: pre0 = (emb[tok]*sqrt(E)) @ W_ih0^T + b_ih0   (M=8192,N=1024,K=1024)
    {
        dim3 g(HH/128, MM/128);
        sgemm_tn<true><<<g, 256>>>(nullptr, emb, inputs, 32.0f,
                                   W_ih0, b_ih0, pre0, HH, HH, HH);
    }

    // Phase B: persistent recurrence (one launch for all 128 steps, no atomics)
    rnn_persist<<<GRIDN, 512, smem_bytes>>>(hidden, pre0,
                                            W_hh0, W_ih1, W_hh1,
                                            b_hh0, b_ih1, b_hh1,
                                            X, outh);

    // Phase C: logits = X @ W_out^T + b_out   (M=8192, N=10000, K=1024)
    {
        dim3 g((VV + 127) / 128, MM / 128);
        sgemm_tn<false><<<g, 256>>>(X, nullptr, nullptr, 1.0f,
                                    W_out, b_out, out, VV, VV, HH);
    }
}